// round 3
// baseline (speedup 1.0000x reference)
#include <cuda_runtime.h>
#include <cuda_bf16.h>
#include <cstdint>

#define HIDDEN 2048
#define NHEADS 32
#define NKV 8
#define HEAD 64
#define BATCH 2
#define SEQ 2048
#define MTOT (BATCH * SEQ)      // 4096
#define KVDIM (NKV * HEAD)      // 512

// ---------------- scratch (__device__ globals; no allocation allowed) -------
__device__ float g_Q[MTOT * HIDDEN];
__device__ float g_K[MTOT * KVDIM];
__device__ float g_V[MTOT * KVDIM];
__device__ float g_attn[MTOT * HIDDEN];

__device__ __nv_bfloat16 g_xh[MTOT * HIDDEN],  g_xl[MTOT * HIDDEN];
__device__ __nv_bfloat16 g_Wqh[HIDDEN * HIDDEN], g_Wql[HIDDEN * HIDDEN];
__device__ __nv_bfloat16 g_Wkh[KVDIM * HIDDEN],  g_Wkl[KVDIM * HIDDEN];
__device__ __nv_bfloat16 g_Wvh[KVDIM * HIDDEN],  g_Wvl[KVDIM * HIDDEN];
__device__ __nv_bfloat16 g_Woh[HIDDEN * HIDDEN], g_Wol[HIDDEN * HIDDEN];
__device__ __nv_bfloat16 g_ah[MTOT * HIDDEN],  g_al[MTOT * HIDDEN];

// ---------------- helpers ----------------------------------------------------
__device__ __forceinline__ uint32_t smem_u32(const void* p) {
    uint32_t a;
    asm("{ .reg .u64 t; cvta.to.shared.u64 t, %1; cvt.u32.u64 %0, t; }"
        : "=r"(a) : "l"(p));
    return a;
}
__device__ __forceinline__ float ex2f(float x) {
    float y;
    asm("ex2.approx.ftz.f32 %0, %1;" : "=f"(y) : "f"(x));
    return y;
}

#define CP16(dst, src) \
    asm volatile("cp.async.cg.shared.global [%0], [%1], 16;" \
                 :: "r"(dst), "l"(src) : "memory")
#define CP_COMMIT() asm volatile("cp.async.commit_group;" ::: "memory")
#define CP_WAIT(N)  asm volatile("cp.async.wait_group %0;" :: "n"(N) : "memory")

__device__ __forceinline__ void ldsm_x4(uint32_t* r, uint32_t addr) {
    asm volatile("ldmatrix.sync.aligned.m8n8.x4.shared.b16 {%0,%1,%2,%3}, [%4];"
                 : "=r"(r[0]), "=r"(r[1]), "=r"(r[2]), "=r"(r[3]) : "r"(addr));
}
__device__ __forceinline__ void mma_bf16(float* c, const uint32_t* a,
                                         const uint32_t* b) {
    asm volatile(
        "mma.sync.aligned.m16n8k16.row.col.f32.bf16.bf16.f32 "
        "{%0,%1,%2,%3}, {%4,%5,%6,%7}, {%8,%9}, {%0,%1,%2,%3};"
        : "+f"(c[0]), "+f"(c[1]), "+f"(c[2]), "+f"(c[3])
        : "r"(a[0]), "r"(a[1]), "r"(a[2]), "r"(a[3]), "r"(b[0]), "r"(b[1]));
}

// ---------------------------------------------------------------------------
// fp32 -> (hi, lo) bf16 split
// ---------------------------------------------------------------------------
__global__ void cvt_split(const float4* __restrict__ in,
                          uint2* __restrict__ hi, uint2* __restrict__ lo, int n4) {
    int i = blockIdx.x * blockDim.x + threadIdx.x;
    if (i >= n4) return;
    float4 v = in[i];
    __nv_bfloat16 hx = __float2bfloat16_rn(v.x);
    __nv_bfloat16 hy = __float2bfloat16_rn(v.y);
    __nv_bfloat16 hz = __float2bfloat16_rn(v.z);
    __nv_bfloat16 hw = __float2bfloat16_rn(v.w);
    __nv_bfloat162 h01 = __nv_bfloat162(hx, hy), h23 = __nv_bfloat162(hz, hw);
    __nv_bfloat162 l01 = __floats2bfloat162_rn(v.x - __bfloat162float(hx),
                                               v.y - __bfloat162float(hy));
    __nv_bfloat162 l23 = __floats2bfloat162_rn(v.z - __bfloat162float(hz),
                                               v.w - __bfloat162float(hw));
    uint2 uh, ul;
    uh.x = *reinterpret_cast<uint32_t*>(&h01);
    uh.y = *reinterpret_cast<uint32_t*>(&h23);
    ul.x = *reinterpret_cast<uint32_t*>(&l01);
    ul.y = *reinterpret_cast<uint32_t*>(&l23);
    hi[i] = uh;
    lo[i] = ul;
}

// ---------------------------------------------------------------------------
// mma.sync split-bf16 GEMM: C[M,N] = A[M,K] * B[N,K]^T (+bias)
// BM=BN=128, BK=32, 256 thr (8 warps, 2x4), warp tile 64x32, cp.async x2 buf.
// smem per part-tile: 128 rows x 80B (32 bf16 + 8 pad)  -> ldmatrix conflict-free
// ---------------------------------------------------------------------------
#define TSTRIDE 80
#define TILE_B (128 * TSTRIDE)           // 10240 bytes per part-tile
#define BUF_B  (4 * TILE_B)              // Ah, Al, Bh, Bl
#define SMEM_GEMM (2 * BUF_B)            // 81920

__device__ __forceinline__ void gemm_tc_body(
    const __nv_bfloat16* __restrict__ Ah, const __nv_bfloat16* __restrict__ Al,
    const __nv_bfloat16* __restrict__ Bh, const __nv_bfloat16* __restrict__ Bl,
    float* __restrict__ C, int N, int K, const float* __restrict__ bias)
{
    extern __shared__ __align__(128) char smem[];
    const int tid = threadIdx.x;
    const int lane = tid & 31;
    const int warp = tid >> 5;
    const int wm = warp >> 2;          // 0..1, 64 rows each
    const int wn = warp & 3;           // 0..3, 32 cols each
    const int m0 = blockIdx.y * 128;
    const int n0 = blockIdx.x * 128;
    const uint32_t sbase = smem_u32(smem);

    const __nv_bfloat16* gsrc[4] = {Ah, Al, Bh, Bl};
    const int row0[4] = {m0, m0, n0, n0};

    // ---- async loader for one K-chunk into buffer `buf`
    auto load_chunk = [&](int c, int buf) {
        const int k0 = c << 5;
        const uint32_t db = sbase + buf * BUF_B;
#pragma unroll
        for (int i = 0; i < 8; i++) {
            int idx = tid + i * 256;       // 0..2047
            int a = idx >> 9;              // which array
            int rem = idx & 511;
            int r = rem >> 2;              // row 0..127
            int q = rem & 3;               // 16B unit in row
            uint32_t dst = db + a * TILE_B + r * TSTRIDE + q * 16;
            const __nv_bfloat16* src = gsrc[a] + (size_t)(row0[a] + r) * K + k0 + q * 8;
            CP16(dst, src);
        }
        CP_COMMIT();
    };

    float acc[4][4][4];
#pragma unroll
    for (int mt = 0; mt < 4; mt++)
#pragma unroll
        for (int nt = 0; nt < 4; nt++)
#pragma unroll
            for (int j = 0; j < 4; j++) acc[mt][nt][j] = 0.f;

    const int NC = K >> 5;
    load_chunk(0, 0);

    // ldmatrix lane addressing (constant per thread)
    const int a_row = lane & 15;             // A: rows
    const int a_cg  = (lane >> 4) * 16;      // A: 16B column group
    const int b_row = (lane & 7) + ((lane >> 4) << 3);  // B: n within 16
    const int b_cg  = ((lane >> 3) & 1) * 16;

    for (int c = 0; c < NC; ++c) {
        const int buf = c & 1;
        if (c + 1 < NC) {
            load_chunk(c + 1, buf ^ 1);
            CP_WAIT(1);
        } else {
            CP_WAIT(0);
        }
        __syncthreads();

        const uint32_t db = sbase + buf * BUF_B;
        const uint32_t sAh = db;
        const uint32_t sAl = db + TILE_B;
        const uint32_t sBh = db + 2 * TILE_B;
        const uint32_t sBl = db + 3 * TILE_B;

#pragma unroll
        for (int ks = 0; ks < 2; ks++) {
            const int kb = ks * 32;  // byte offset for k-step (16 bf16)
            uint32_t aH[4][4], aL[4][4], bH[2][4], bL[2][4];
#pragma unroll
            for (int mt = 0; mt < 4; mt++) {
                uint32_t off = (uint32_t)(wm * 64 + mt * 16 + a_row) * TSTRIDE + a_cg + kb;
                ldsm_x4(aH[mt], sAh + off);
                ldsm_x4(aL[mt], sAl + off);
            }
#pragma unroll
            for (int np = 0; np < 2; np++) {
                uint32_t off = (uint32_t)(wn * 32 + np * 16 + b_row) * TSTRIDE + b_cg + kb;
                ldsm_x4(bH[np], sBh + off);
                ldsm_x4(bL[np], sBl + off);
            }
#pragma unroll
            for (int mt = 0; mt < 4; mt++)
#pragma unroll
                for (int np = 0; np < 2; np++) {
                    mma_bf16(acc[mt][2 * np + 0], aH[mt], &bH[np][0]);
                    mma_bf16(acc[mt][2 * np + 1], aH[mt], &bH[np][2]);
                    mma_bf16(acc[mt][2 * np + 0], aH[mt], &bL[np][0]);
                    mma_bf16(acc[mt][2 * np + 1], aH[mt], &bL[np][2]);
                    mma_bf16(acc[mt][2 * np + 0], aL[mt], &bH[np][0]);
                    mma_bf16(acc[mt][2 * np + 1], aL[mt], &bH[np][2]);
                }
        }
        __syncthreads();
    }

    // ---- epilogue: fragment -> global
    const int frow = lane >> 2;
    const int fcol = (lane & 3) * 2;
#pragma unroll
    for (int mt = 0; mt < 4; mt++) {
#pragma unroll
        for (int nt = 0; nt < 4; nt++) {
            int row = m0 + wm * 64 + mt * 16 + frow;
            int col = n0 + wn * 32 + nt * 8 + fcol;
            float b0 = 0.f, b1 = 0.f;
            if (bias) { b0 = bias[col]; b1 = bias[col + 1]; }
            float2 v0 = make_float2(acc[mt][nt][0] + b0, acc[mt][nt][1] + b1);
            float2 v1 = make_float2(acc[mt][nt][2] + b0, acc[mt][nt][3] + b1);
            *(float2*)(C + (size_t)row * N + col) = v0;
            *(float2*)(C + (size_t)(row + 8) * N + col) = v1;
        }
    }
}

__global__ __launch_bounds__(256)
void gemm_tc(const __nv_bfloat16* __restrict__ Ah, const __nv_bfloat16* __restrict__ Al,
             const __nv_bfloat16* __restrict__ Bh, const __nv_bfloat16* __restrict__ Bl,
             float* __restrict__ C, int N, int K, const float* __restrict__ bias)
{
    gemm_tc_body(Ah, Al, Bh, Bl, C, N, K, bias);
}

__global__ __launch_bounds__(256)
void gemm_tc_kv(const __nv_bfloat16* __restrict__ xh, const __nv_bfloat16* __restrict__ xl,
                const __nv_bfloat16* __restrict__ Wkh, const __nv_bfloat16* __restrict__ Wkl,
                const __nv_bfloat16* __restrict__ Wvh, const __nv_bfloat16* __restrict__ Wvl,
                float* __restrict__ Ck, float* __restrict__ Cv, int N, int K)
{
    if (blockIdx.z == 0)
        gemm_tc_body(xh, xl, Wkh, Wkl, Ck, N, K, nullptr);
    else
        gemm_tc_body(xh, xl, Wvh, Wvl, Cv, N, K, nullptr);
}

// ---------------------------------------------------------------------------
// Flash attention (fp32 SIMT, unchanged from round 1)
// ---------------------------------------------------------------------------
__global__ __launch_bounds__(256, 2)
void flash_attn_kernel()
{
    extern __shared__ __align__(16) float sm[];
    float* Qst = sm;
    float* Kst = sm + 64 * 64;
    float* Vs  = sm + 2 * 64 * 64;
    float* Ps  = sm + 3 * 64 * 64;

    const int tid = threadIdx.x;
    const int tx = tid & 15;
    const int ty = tid >> 4;
    const int q0 = blockIdx.x * 64;
    const int h  = blockIdx.y;
    const int b  = blockIdx.z;
    const int kvh = h >> 2;

    const float* Qg = g_Q + (size_t)(b * SEQ + q0) * HIDDEN + h * HEAD;
    const float* Kg = g_K + (size_t)(b * SEQ) * KVDIM + kvh * HEAD;
    const float* Vg = g_V + (size_t)(b * SEQ) * KVDIM + kvh * HEAD;

    const float sc = 0.125f * 1.4426950408889634f;

#pragma unroll
    for (int i = 0; i < 4; i++) {
        int id = tid + i * 256;
        int row = id >> 4;
        int d = (id & 15) << 2;
        float4 q = *(const float4*)(Qg + (size_t)row * HIDDEN + d);
        Qst[(d + 0) * 64 + row] = q.x * sc;
        Qst[(d + 1) * 64 + row] = q.y * sc;
        Qst[(d + 2) * 64 + row] = q.z * sc;
        Qst[(d + 3) * 64 + row] = q.w * sc;
    }

    float mrow[4], lacc[4], o[4][4];
#pragma unroll
    for (int r = 0; r < 4; r++) {
        mrow[r] = -1e30f;
        lacc[r] = 0.f;
#pragma unroll
        for (int j = 0; j < 4; j++) o[r][j] = 0.f;
    }

    for (int kv0 = 0; kv0 < SEQ; kv0 += 64) {
        __syncthreads();
#pragma unroll
        for (int i = 0; i < 4; i++) {
            int id = tid + i * 256;
            int row = id >> 4;
            int d = (id & 15) << 2;
            float4 k4 = *(const float4*)(Kg + (size_t)(kv0 + row) * KVDIM + d);
            int swr = row ^ (d & 60);
            Kst[(d + 0) * 64 + swr] = k4.x;
            Kst[(d + 1) * 64 + swr] = k4.y;
            Kst[(d + 2) * 64 + swr] = k4.z;
            Kst[(d + 3) * 64 + swr] = k4.w;
            float4 v4 = *(const float4*)(Vg + (size_t)(kv0 + row) * KVDIM + d);
            *(float4*)&Vs[row * 64 + d] = v4;
        }
        __syncthreads();

        float s[4][4];
#pragma unroll
        for (int r = 0; r < 4; r++)
#pragma unroll
            for (int c = 0; c < 4; c++) s[r][c] = 0.f;

#pragma unroll 16
        for (int d = 0; d < 64; d++) {
            float4 q = *(const float4*)&Qst[d * 64 + ty * 4];
            float4 k = *(const float4*)&Kst[d * 64 + ((tx * 4) ^ (d & 60))];
            s[0][0] = fmaf(q.x, k.x, s[0][0]);
            s[0][1] = fmaf(q.x, k.y, s[0][1]);
            s[0][2] = fmaf(q.x, k.z, s[0][2]);
            s[0][3] = fmaf(q.x, k.w, s[0][3]);
            s[1][0] = fmaf(q.y, k.x, s[1][0]);
            s[1][1] = fmaf(q.y, k.y, s[1][1]);
            s[1][2] = fmaf(q.y, k.z, s[1][2]);
            s[1][3] = fmaf(q.y, k.w, s[1][3]);
            s[2][0] = fmaf(q.z, k.x, s[2][0]);
            s[2][1] = fmaf(q.z, k.y, s[2][1]);
            s[2][2] = fmaf(q.z, k.z, s[2][2]);
            s[2][3] = fmaf(q.z, k.w, s[2][3]);
            s[3][0] = fmaf(q.w, k.x, s[3][0]);
            s[3][1] = fmaf(q.w, k.y, s[3][1]);
            s[3][2] = fmaf(q.w, k.z, s[3][2]);
            s[3][3] = fmaf(q.w, k.w, s[3][3]);
        }

#pragma unroll
        for (int r = 0; r < 4; r++) {
            float mx = fmaxf(fmaxf(s[r][0], s[r][1]), fmaxf(s[r][2], s[r][3]));
#pragma unroll
            for (int off = 8; off >= 1; off >>= 1)
                mx = fmaxf(mx, __shfl_xor_sync(0xffffffffu, mx, off));
            float mnew = fmaxf(mrow[r], mx);
            float alpha = ex2f(mrow[r] - mnew);
            mrow[r] = mnew;
            float p0 = ex2f(s[r][0] - mnew);
            float p1 = ex2f(s[r][1] - mnew);
            float p2 = ex2f(s[r][2] - mnew);
            float p3 = ex2f(s[r][3] - mnew);
            float rs = (p0 + p1) + (p2 + p3);
#pragma unroll
            for (int off = 8; off >= 1; off >>= 1)
                rs += __shfl_xor_sync(0xffffffffu, rs, off);
            lacc[r] = lacc[r] * alpha + rs;
            o[r][0] *= alpha;
            o[r][1] *= alpha;
            o[r][2] *= alpha;
            o[r][3] *= alpha;
            *(float4*)&Ps[(ty * 4 + r) * 64 + tx * 4] = make_float4(p0, p1, p2, p3);
        }
        __syncthreads();

#pragma unroll 16
        for (int kv = 0; kv < 64; kv++) {
            float4 v = *(const float4*)&Vs[kv * 64 + tx * 4];
            float pa = Ps[(ty * 4 + 0) * 64 + kv];
            float pb = Ps[(ty * 4 + 1) * 64 + kv];
            float pc = Ps[(ty * 4 + 2) * 64 + kv];
            float pd = Ps[(ty * 4 + 3) * 64 + kv];
            o[0][0] = fmaf(pa, v.x, o[0][0]);
            o[0][1] = fmaf(pa, v.y, o[0][1]);
            o[0][2] = fmaf(pa, v.z, o[0][2]);
            o[0][3] = fmaf(pa, v.w, o[0][3]);
            o[1][0] = fmaf(pb, v.x, o[1][0]);
            o[1][1] = fmaf(pb, v.y, o[1][1]);
            o[1][2] = fmaf(pb, v.z, o[1][2]);
            o[1][3] = fmaf(pb, v.w, o[1][3]);
            o[2][0] = fmaf(pc, v.x, o[2][0]);
            o[2][1] = fmaf(pc, v.y, o[2][1]);
            o[2][2] = fmaf(pc, v.z, o[2][2]);
            o[2][3] = fmaf(pc, v.w, o[2][3]);
            o[3][0] = fmaf(pd, v.x, o[3][0]);
            o[3][1] = fmaf(pd, v.y, o[3][1]);
            o[3][2] = fmaf(pd, v.z, o[3][2]);
            o[3][3] = fmaf(pd, v.w, o[3][3]);
        }
    }

    float* Og = g_attn + (size_t)(b * SEQ + q0) * HIDDEN + h * HEAD;
#pragma unroll
    for (int r = 0; r < 4; r++) {
        float inv = 1.f / lacc[r];
        float4 ov = make_float4(o[r][0] * inv, o[r][1] * inv,
                                o[r][2] * inv, o[r][3] * inv);
        *(float4*)(Og + (size_t)(ty * 4 + r) * HIDDEN + tx * 4) = ov;
    }
}

// ---------------------------------------------------------------------------

extern "C" void kernel_launch(void* const* d_in, const int* in_sizes, int n_in,
                              void* d_out, int out_size)
{
    const float* x  = (const float*)d_in[0];
    const float* Wq = (const float*)d_in[1];
    const float* Wk = (const float*)d_in[2];
    const float* Wv = (const float*)d_in[3];
    const float* Wo = (const float*)d_in[4];
    const float* bo = (const float*)d_in[5];
    float* out = (float*)d_out;

    float *Qp, *Kp, *Vp, *Ap;
    cudaGetSymbolAddress((void**)&Qp, g_Q);
    cudaGetSymbolAddress((void**)&Kp, g_K);
    cudaGetSymbolAddress((void**)&Vp, g_V);
    cudaGetSymbolAddress((void**)&Ap, g_attn);

    __nv_bfloat16 *xh, *xl, *Wqh, *Wql, *Wkh, *Wkl, *Wvh, *Wvl, *Woh, *Wol, *ah, *al;
    cudaGetSymbolAddress((void**)&xh, g_xh);   cudaGetSymbolAddress((void**)&xl, g_xl);
    cudaGetSymbolAddress((void**)&Wqh, g_Wqh); cudaGetSymbolAddress((void**)&Wql, g_Wql);
    cudaGetSymbolAddress((void**)&Wkh, g_Wkh); cudaGetSymbolAddress((void**)&Wkl, g_Wkl);
    cudaGetSymbolAddress((void**)&Wvh, g_Wvh); cudaGetSymbolAddress((void**)&Wvl, g_Wvl);
    cudaGetSymbolAddress((void**)&Woh, g_Woh); cudaGetSymbolAddress((void**)&Wol, g_Wol);
    cudaGetSymbolAddress((void**)&ah, g_ah);   cudaGetSymbolAddress((void**)&al, g_al);

    cudaFuncSetAttribute(gemm_tc, cudaFuncAttributeMaxDynamicSharedMemorySize, SMEM_GEMM);
    cudaFuncSetAttribute(gemm_tc_kv, cudaFuncAttributeMaxDynamicSharedMemorySize, SMEM_GEMM);
    const int smem_flash = 4 * 64 * 64 * (int)sizeof(float);  // 64 KB
    cudaFuncSetAttribute(flash_attn_kernel,
                         cudaFuncAttributeMaxDynamicSharedMemorySize, smem_flash);

    // fp32 -> bf16 hi/lo splits
    {
        int n4;
        n4 = MTOT * HIDDEN / 4;
        cvt_split<<<n4 / 256, 256>>>((const float4*)x, (uint2*)xh, (uint2*)xl, n4);
        n4 = HIDDEN * HIDDEN / 4;
        cvt_split<<<n4 / 256, 256>>>((const float4*)Wq, (uint2*)Wqh, (uint2*)Wql, n4);
        n4 = KVDIM * HIDDEN / 4;
        cvt_split<<<n4 / 256, 256>>>((const float4*)Wk, (uint2*)Wkh, (uint2*)Wkl, n4);
        cvt_split<<<n4 / 256, 256>>>((const float4*)Wv, (uint2*)Wvh, (uint2*)Wvl, n4);
        n4 = HIDDEN * HIDDEN / 4;
        cvt_split<<<n4 / 256, 256>>>((const float4*)Wo, (uint2*)Woh, (uint2*)Wol, n4);
    }

    // Q projection
    gemm_tc<<<dim3(HIDDEN / 128, MTOT / 128), 256, SMEM_GEMM>>>(
        xh, xl, Wqh, Wql, Qp, HIDDEN, HIDDEN, nullptr);
    // K and V projections (fused via z)
    gemm_tc_kv<<<dim3(KVDIM / 128, MTOT / 128, 2), 256, SMEM_GEMM>>>(
        xh, xl, Wkh, Wkl, Wvh, Wvl, Kp, Vp, KVDIM, HIDDEN);
    // Attention
    flash_attn_kernel<<<dim3(SEQ / 64, NHEADS, BATCH), 256, smem_flash>>>();
    // attn -> bf16 split, then output projection + bias
    {
        int n4 = MTOT * HIDDEN / 4;
        cvt_split<<<n4 / 256, 256>>>((const float4*)Ap, (uint2*)ah, (uint2*)al, n4);
    }
    gemm_tc<<<dim3(HIDDEN / 128, MTOT / 128), 256, SMEM_GEMM>>>(
        ah, al, Woh, Wol, out, HIDDEN, HIDDEN, bo);
}

// round 4
// speedup vs baseline: 1.6133x; 1.6133x over previous
#include <cuda_runtime.h>
#include <cuda_bf16.h>
#include <cstdint>

#define HIDDEN 2048
#define NHEADS 32
#define NKV 8
#define HEAD 64
#define BATCH 2
#define SEQ 2048
#define MTOT (BATCH * SEQ)      // 4096
#define KVDIM (NKV * HEAD)      // 512

// ---------------- scratch (__device__ globals; no allocation allowed) -------
__device__ float g_Q[MTOT * HIDDEN];
__device__ float g_K[MTOT * KVDIM];
__device__ float g_V[MTOT * KVDIM];
__device__ float g_attn[MTOT * HIDDEN];

__device__ __nv_bfloat16 g_xh[MTOT * HIDDEN],  g_xl[MTOT * HIDDEN];
__device__ __nv_bfloat16 g_Wqh[HIDDEN * HIDDEN], g_Wql[HIDDEN * HIDDEN];
__device__ __nv_bfloat16 g_Wkh[KVDIM * HIDDEN],  g_Wkl[KVDIM * HIDDEN];
__device__ __nv_bfloat16 g_Wvh[KVDIM * HIDDEN],  g_Wvl[KVDIM * HIDDEN];
__device__ __nv_bfloat16 g_Woh[HIDDEN * HIDDEN], g_Wol[HIDDEN * HIDDEN];
__device__ __nv_bfloat16 g_ah[MTOT * HIDDEN],  g_al[MTOT * HIDDEN];

// ---------------- helpers ----------------------------------------------------
__device__ __forceinline__ uint32_t smem_u32(const void* p) {
    uint32_t a;
    asm("{ .reg .u64 t; cvta.to.shared.u64 t, %1; cvt.u32.u64 %0, t; }"
        : "=r"(a) : "l"(p));
    return a;
}
__device__ __forceinline__ float ex2f(float x) {
    float y;
    asm("ex2.approx.ftz.f32 %0, %1;" : "=f"(y) : "f"(x));
    return y;
}

#define CP16(dst, src) \
    asm volatile("cp.async.cg.shared.global [%0], [%1], 16;" \
                 :: "r"(dst), "l"(src) : "memory")
#define CP_COMMIT() asm volatile("cp.async.commit_group;" ::: "memory")
#define CP_WAIT(N)  asm volatile("cp.async.wait_group %0;" :: "n"(N) : "memory")

__device__ __forceinline__ void ldsm_x4(uint32_t* r, uint32_t addr) {
    asm volatile("ldmatrix.sync.aligned.m8n8.x4.shared.b16 {%0,%1,%2,%3}, [%4];"
                 : "=r"(r[0]), "=r"(r[1]), "=r"(r[2]), "=r"(r[3]) : "r"(addr));
}
__device__ __forceinline__ void mma_bf16(float* c, const uint32_t* a,
                                         const uint32_t* b) {
    asm volatile(
        "mma.sync.aligned.m16n8k16.row.col.f32.bf16.bf16.f32 "
        "{%0,%1,%2,%3}, {%4,%5,%6,%7}, {%8,%9}, {%0,%1,%2,%3};"
        : "+f"(c[0]), "+f"(c[1]), "+f"(c[2]), "+f"(c[3])
        : "r"(a[0]), "r"(a[1]), "r"(a[2]), "r"(a[3]), "r"(b[0]), "r"(b[1]));
}

// ---------------------------------------------------------------------------
// fp32 -> (hi, lo) bf16 split
// ---------------------------------------------------------------------------
__global__ void cvt_split(const float4* __restrict__ in,
                          uint2* __restrict__ hi, uint2* __restrict__ lo, int n4) {
    int i = blockIdx.x * blockDim.x + threadIdx.x;
    if (i >= n4) return;
    float4 v = in[i];
    __nv_bfloat16 hx = __float2bfloat16_rn(v.x);
    __nv_bfloat16 hy = __float2bfloat16_rn(v.y);
    __nv_bfloat16 hz = __float2bfloat16_rn(v.z);
    __nv_bfloat16 hw = __float2bfloat16_rn(v.w);
    __nv_bfloat162 h01 = __nv_bfloat162(hx, hy), h23 = __nv_bfloat162(hz, hw);
    __nv_bfloat162 l01 = __floats2bfloat162_rn(v.x - __bfloat162float(hx),
                                               v.y - __bfloat162float(hy));
    __nv_bfloat162 l23 = __floats2bfloat162_rn(v.z - __bfloat162float(hz),
                                               v.w - __bfloat162float(hw));
    uint2 uh, ul;
    uh.x = *reinterpret_cast<uint32_t*>(&h01);
    uh.y = *reinterpret_cast<uint32_t*>(&h23);
    ul.x = *reinterpret_cast<uint32_t*>(&l01);
    ul.y = *reinterpret_cast<uint32_t*>(&l23);
    hi[i] = uh;
    lo[i] = ul;
}

// ---------------------------------------------------------------------------
// mma.sync split-bf16 GEMM: C[M,N] = A[M,K] * B[N,K]^T (+bias)
// BM=BN=128, BK=32, 256 thr (8 warps, 2x4), warp tile 64x32, cp.async x2 buf.
// Pass-ordered inner loop: accumulator reuse distance = 16 MMAs (covers HMMA
// RAW latency), vs 2 in the previous round.
// ---------------------------------------------------------------------------
#define TSTRIDE 80
#define TILE_B (128 * TSTRIDE)           // 10240 bytes per part-tile
#define BUF_B  (4 * TILE_B)              // Ah, Al, Bh, Bl
#define SMEM_GEMM (2 * BUF_B)            // 81920

__device__ __forceinline__ void gemm_tc_body(
    const __nv_bfloat16* __restrict__ Ah, const __nv_bfloat16* __restrict__ Al,
    const __nv_bfloat16* __restrict__ Bh, const __nv_bfloat16* __restrict__ Bl,
    float* __restrict__ C, int N, int K, const float* __restrict__ bias)
{
    extern __shared__ __align__(128) char smem[];
    const int tid = threadIdx.x;
    const int lane = tid & 31;
    const int warp = tid >> 5;
    const int wm = warp >> 2;          // 0..1, 64 rows each
    const int wn = warp & 3;           // 0..3, 32 cols each
    const int m0 = blockIdx.y * 128;
    const int n0 = blockIdx.x * 128;
    const uint32_t sbase = smem_u32(smem);

    const __nv_bfloat16* gsrc[4] = {Ah, Al, Bh, Bl};
    const int row0[4] = {m0, m0, n0, n0};

    auto load_chunk = [&](int c, int buf) {
        const int k0 = c << 5;
        const uint32_t db = sbase + buf * BUF_B;
#pragma unroll
        for (int i = 0; i < 8; i++) {
            int idx = tid + i * 256;       // 0..2047
            int a = idx >> 9;              // which array (constant per i)
            int rem = idx & 511;
            int r = rem >> 2;              // row 0..127
            int q = rem & 3;               // 16B unit in row
            uint32_t dst = db + a * TILE_B + r * TSTRIDE + q * 16;
            const __nv_bfloat16* src = gsrc[a] + (size_t)(row0[a] + r) * K + k0 + q * 8;
            CP16(dst, src);
        }
        CP_COMMIT();
    };

    float acc[4][4][4];
#pragma unroll
    for (int mt = 0; mt < 4; mt++)
#pragma unroll
        for (int nt = 0; nt < 4; nt++)
#pragma unroll
            for (int j = 0; j < 4; j++) acc[mt][nt][j] = 0.f;

    const int NC = K >> 5;
    load_chunk(0, 0);

    const int a_row = lane & 15;
    const int a_cg  = (lane >> 4) * 16;
    const int b_row = (lane & 7) + ((lane >> 4) << 3);
    const int b_cg  = ((lane >> 3) & 1) * 16;

    for (int c = 0; c < NC; ++c) {
        const int buf = c & 1;
        if (c + 1 < NC) {
            load_chunk(c + 1, buf ^ 1);
            CP_WAIT(1);
        } else {
            CP_WAIT(0);
        }
        __syncthreads();

        const uint32_t db = sbase + buf * BUF_B;
        const uint32_t sAh = db;
        const uint32_t sAl = db + TILE_B;
        const uint32_t sBh = db + 2 * TILE_B;
        const uint32_t sBl = db + 3 * TILE_B;

#pragma unroll
        for (int ks = 0; ks < 2; ks++) {
            const int kb = ks * 32;  // byte offset for k-step (16 bf16)
            uint32_t aH[4][4], aL[4][4], bH[2][4], bL[2][4];
#pragma unroll
            for (int mt = 0; mt < 4; mt++) {
                uint32_t off = (uint32_t)(wm * 64 + mt * 16 + a_row) * TSTRIDE + a_cg + kb;
                ldsm_x4(aH[mt], sAh + off);
            }
#pragma unroll
            for (int np = 0; np < 2; np++) {
                uint32_t off = (uint32_t)(wn * 32 + np * 16 + b_row) * TSTRIDE + b_cg + kb;
                ldsm_x4(bH[np], sBh + off);
                ldsm_x4(bL[np], sBl + off);
            }
            // pass 1: Ah * Bh  (16 MMAs, 16 distinct accumulators)
#pragma unroll
            for (int mt = 0; mt < 4; mt++)
#pragma unroll
                for (int np = 0; np < 2; np++) {
                    mma_bf16(acc[mt][2 * np + 0], aH[mt], &bH[np][0]);
                    mma_bf16(acc[mt][2 * np + 1], aH[mt], &bH[np][2]);
                }
            // pass 2: Ah * Bl
#pragma unroll
            for (int mt = 0; mt < 4; mt++)
#pragma unroll
                for (int np = 0; np < 2; np++) {
                    mma_bf16(acc[mt][2 * np + 0], aH[mt], &bL[np][0]);
                    mma_bf16(acc[mt][2 * np + 1], aH[mt], &bL[np][2]);
                }
            // load Al fragments, then pass 3: Al * Bh
#pragma unroll
            for (int mt = 0; mt < 4; mt++) {
                uint32_t off = (uint32_t)(wm * 64 + mt * 16 + a_row) * TSTRIDE + a_cg + kb;
                ldsm_x4(aL[mt], sAl + off);
            }
#pragma unroll
            for (int mt = 0; mt < 4; mt++)
#pragma unroll
                for (int np = 0; np < 2; np++) {
                    mma_bf16(acc[mt][2 * np + 0], aL[mt], &bH[np][0]);
                    mma_bf16(acc[mt][2 * np + 1], aL[mt], &bH[np][2]);
                }
        }
        __syncthreads();
    }

    const int frow = lane >> 2;
    const int fcol = (lane & 3) * 2;
#pragma unroll
    for (int mt = 0; mt < 4; mt++) {
#pragma unroll
        for (int nt = 0; nt < 4; nt++) {
            int row = m0 + wm * 64 + mt * 16 + frow;
            int col = n0 + wn * 32 + nt * 8 + fcol;
            float b0 = 0.f, b1 = 0.f;
            if (bias) { b0 = bias[col]; b1 = bias[col + 1]; }
            float2 v0 = make_float2(acc[mt][nt][0] + b0, acc[mt][nt][1] + b1);
            float2 v1 = make_float2(acc[mt][nt][2] + b0, acc[mt][nt][3] + b1);
            *(float2*)(C + (size_t)row * N + col) = v0;
            *(float2*)(C + (size_t)(row + 8) * N + col) = v1;
        }
    }
}

__global__ __launch_bounds__(256)
void gemm_tc(const __nv_bfloat16* __restrict__ Ah, const __nv_bfloat16* __restrict__ Al,
             const __nv_bfloat16* __restrict__ Bh, const __nv_bfloat16* __restrict__ Bl,
             float* __restrict__ C, int N, int K, const float* __restrict__ bias)
{
    gemm_tc_body(Ah, Al, Bh, Bl, C, N, K, bias);
}

__global__ __launch_bounds__(256)
void gemm_tc_kv(const __nv_bfloat16* __restrict__ xh, const __nv_bfloat16* __restrict__ xl,
                const __nv_bfloat16* __restrict__ Wkh, const __nv_bfloat16* __restrict__ Wkl,
                const __nv_bfloat16* __restrict__ Wvh, const __nv_bfloat16* __restrict__ Wvl,
                float* __restrict__ Ck, float* __restrict__ Cv, int N, int K)
{
    if (blockIdx.z == 0)
        gemm_tc_body(xh, xl, Wkh, Wkl, Ck, N, K, nullptr);
    else
        gemm_tc_body(xh, xl, Wvh, Wvl, Cv, N, K, nullptr);
}

// ---------------------------------------------------------------------------
// Flash attention (fp32 SIMT, unchanged)
// ---------------------------------------------------------------------------
__global__ __launch_bounds__(256, 2)
void flash_attn_kernel()
{
    extern __shared__ __align__(16) float sm[];
    float* Qst = sm;
    float* Kst = sm + 64 * 64;
    float* Vs  = sm + 2 * 64 * 64;
    float* Ps  = sm + 3 * 64 * 64;

    const int tid = threadIdx.x;
    const int tx = tid & 15;
    const int ty = tid >> 4;
    const int q0 = blockIdx.x * 64;
    const int h  = blockIdx.y;
    const int b  = blockIdx.z;
    const int kvh = h >> 2;

    const float* Qg = g_Q + (size_t)(b * SEQ + q0) * HIDDEN + h * HEAD;
    const float* Kg = g_K + (size_t)(b * SEQ) * KVDIM + kvh * HEAD;
    const float* Vg = g_V + (size_t)(b * SEQ) * KVDIM + kvh * HEAD;

    const float sc = 0.125f * 1.4426950408889634f;

#pragma unroll
    for (int i = 0; i < 4; i++) {
        int id = tid + i * 256;
        int row = id >> 4;
        int d = (id & 15) << 2;
        float4 q = *(const float4*)(Qg + (size_t)row * HIDDEN + d);
        Qst[(d + 0) * 64 + row] = q.x * sc;
        Qst[(d + 1) * 64 + row] = q.y * sc;
        Qst[(d + 2) * 64 + row] = q.z * sc;
        Qst[(d + 3) * 64 + row] = q.w * sc;
    }

    float mrow[4], lacc[4], o[4][4];
#pragma unroll
    for (int r = 0; r < 4; r++) {
        mrow[r] = -1e30f;
        lacc[r] = 0.f;
#pragma unroll
        for (int j = 0; j < 4; j++) o[r][j] = 0.f;
    }

    for (int kv0 = 0; kv0 < SEQ; kv0 += 64) {
        __syncthreads();
#pragma unroll
        for (int i = 0; i < 4; i++) {
            int id = tid + i * 256;
            int row = id >> 4;
            int d = (id & 15) << 2;
            float4 k4 = *(const float4*)(Kg + (size_t)(kv0 + row) * KVDIM + d);
            int swr = row ^ (d & 60);
            Kst[(d + 0) * 64 + swr] = k4.x;
            Kst[(d + 1) * 64 + swr] = k4.y;
            Kst[(d + 2) * 64 + swr] = k4.z;
            Kst[(d + 3) * 64 + swr] = k4.w;
            float4 v4 = *(const float4*)(Vg + (size_t)(kv0 + row) * KVDIM + d);
            *(float4*)&Vs[row * 64 + d] = v4;
        }
        __syncthreads();

        float s[4][4];
#pragma unroll
        for (int r = 0; r < 4; r++)
#pragma unroll
            for (int c = 0; c < 4; c++) s[r][c] = 0.f;

#pragma unroll 16
        for (int d = 0; d < 64; d++) {
            float4 q = *(const float4*)&Qst[d * 64 + ty * 4];
            float4 k = *(const float4*)&Kst[d * 64 + ((tx * 4) ^ (d & 60))];
            s[0][0] = fmaf(q.x, k.x, s[0][0]);
            s[0][1] = fmaf(q.x, k.y, s[0][1]);
            s[0][2] = fmaf(q.x, k.z, s[0][2]);
            s[0][3] = fmaf(q.x, k.w, s[0][3]);
            s[1][0] = fmaf(q.y, k.x, s[1][0]);
            s[1][1] = fmaf(q.y, k.y, s[1][1]);
            s[1][2] = fmaf(q.y, k.z, s[1][2]);
            s[1][3] = fmaf(q.y, k.w, s[1][3]);
            s[2][0] = fmaf(q.z, k.x, s[2][0]);
            s[2][1] = fmaf(q.z, k.y, s[2][1]);
            s[2][2] = fmaf(q.z, k.z, s[2][2]);
            s[2][3] = fmaf(q.z, k.w, s[2][3]);
            s[3][0] = fmaf(q.w, k.x, s[3][0]);
            s[3][1] = fmaf(q.w, k.y, s[3][1]);
            s[3][2] = fmaf(q.w, k.z, s[3][2]);
            s[3][3] = fmaf(q.w, k.w, s[3][3]);
        }

#pragma unroll
        for (int r = 0; r < 4; r++) {
            float mx = fmaxf(fmaxf(s[r][0], s[r][1]), fmaxf(s[r][2], s[r][3]));
#pragma unroll
            for (int off = 8; off >= 1; off >>= 1)
                mx = fmaxf(mx, __shfl_xor_sync(0xffffffffu, mx, off));
            float mnew = fmaxf(mrow[r], mx);
            float alpha = ex2f(mrow[r] - mnew);
            mrow[r] = mnew;
            float p0 = ex2f(s[r][0] - mnew);
            float p1 = ex2f(s[r][1] - mnew);
            float p2 = ex2f(s[r][2] - mnew);
            float p3 = ex2f(s[r][3] - mnew);
            float rs = (p0 + p1) + (p2 + p3);
#pragma unroll
            for (int off = 8; off >= 1; off >>= 1)
                rs += __shfl_xor_sync(0xffffffffu, rs, off);
            lacc[r] = lacc[r] * alpha + rs;
            o[r][0] *= alpha;
            o[r][1] *= alpha;
            o[r][2] *= alpha;
            o[r][3] *= alpha;
            *(float4*)&Ps[(ty * 4 + r) * 64 + tx * 4] = make_float4(p0, p1, p2, p3);
        }
        __syncthreads();

#pragma unroll 16
        for (int kv = 0; kv < 64; kv++) {
            float4 v = *(const float4*)&Vs[kv * 64 + tx * 4];
            float pa = Ps[(ty * 4 + 0) * 64 + kv];
            float pb = Ps[(ty * 4 + 1) * 64 + kv];
            float pc = Ps[(ty * 4 + 2) * 64 + kv];
            float pd = Ps[(ty * 4 + 3) * 64 + kv];
            o[0][0] = fmaf(pa, v.x, o[0][0]);
            o[0][1] = fmaf(pa, v.y, o[0][1]);
            o[0][2] = fmaf(pa, v.z, o[0][2]);
            o[0][3] = fmaf(pa, v.w, o[0][3]);
            o[1][0] = fmaf(pb, v.x, o[1][0]);
            o[1][1] = fmaf(pb, v.y, o[1][1]);
            o[1][2] = fmaf(pb, v.z, o[1][2]);
            o[1][3] = fmaf(pb, v.w, o[1][3]);
            o[2][0] = fmaf(pc, v.x, o[2][0]);
            o[2][1] = fmaf(pc, v.y, o[2][1]);
            o[2][2] = fmaf(pc, v.z, o[2][2]);
            o[2][3] = fmaf(pc, v.w, o[2][3]);
            o[3][0] = fmaf(pd, v.x, o[3][0]);
            o[3][1] = fmaf(pd, v.y, o[3][1]);
            o[3][2] = fmaf(pd, v.z, o[3][2]);
            o[3][3] = fmaf(pd, v.w, o[3][3]);
        }
    }

    float* Og = g_attn + (size_t)(b * SEQ + q0) * HIDDEN + h * HEAD;
#pragma unroll
    for (int r = 0; r < 4; r++) {
        float inv = 1.f / lacc[r];
        float4 ov = make_float4(o[r][0] * inv, o[r][1] * inv,
                                o[r][2] * inv, o[r][3] * inv);
        *(float4*)(Og + (size_t)(ty * 4 + r) * HIDDEN + tx * 4) = ov;
    }
}

// ---------------------------------------------------------------------------

extern "C" void kernel_launch(void* const* d_in, const int* in_sizes, int n_in,
                              void* d_out, int out_size)
{
    const float* x  = (const float*)d_in[0];
    const float* Wq = (const float*)d_in[1];
    const float* Wk = (const float*)d_in[2];
    const float* Wv = (const float*)d_in[3];
    const float* Wo = (const float*)d_in[4];
    const float* bo = (const float*)d_in[5];
    float* out = (float*)d_out;

    float *Qp, *Kp, *Vp, *Ap;
    cudaGetSymbolAddress((void**)&Qp, g_Q);
    cudaGetSymbolAddress((void**)&Kp, g_K);
    cudaGetSymbolAddress((void**)&Vp, g_V);
    cudaGetSymbolAddress((void**)&Ap, g_attn);

    __nv_bfloat16 *xh, *xl, *Wqh, *Wql, *Wkh, *Wkl, *Wvh, *Wvl, *Woh, *Wol, *ah, *al;
    cudaGetSymbolAddress((void**)&xh, g_xh);   cudaGetSymbolAddress((void**)&xl, g_xl);
    cudaGetSymbolAddress((void**)&Wqh, g_Wqh); cudaGetSymbolAddress((void**)&Wql, g_Wql);
    cudaGetSymbolAddress((void**)&Wkh, g_Wkh); cudaGetSymbolAddress((void**)&Wkl, g_Wkl);
    cudaGetSymbolAddress((void**)&Wvh, g_Wvh); cudaGetSymbolAddress((void**)&Wvl, g_Wvl);
    cudaGetSymbolAddress((void**)&Woh, g_Woh); cudaGetSymbolAddress((void**)&Wol, g_Wol);
    cudaGetSymbolAddress((void**)&ah, g_ah);   cudaGetSymbolAddress((void**)&al, g_al);

    cudaFuncSetAttribute(gemm_tc, cudaFuncAttributeMaxDynamicSharedMemorySize, SMEM_GEMM);
    cudaFuncSetAttribute(gemm_tc_kv, cudaFuncAttributeMaxDynamicSharedMemorySize, SMEM_GEMM);
    const int smem_flash = 4 * 64 * 64 * (int)sizeof(float);  // 64 KB
    cudaFuncSetAttribute(flash_attn_kernel,
                         cudaFuncAttributeMaxDynamicSharedMemorySize, smem_flash);

    {
        int n4;
        n4 = MTOT * HIDDEN / 4;
        cvt_split<<<n4 / 256, 256>>>((const float4*)x, (uint2*)xh, (uint2*)xl, n4);
        n4 = HIDDEN * HIDDEN / 4;
        cvt_split<<<n4 / 256, 256>>>((const float4*)Wq, (uint2*)Wqh, (uint2*)Wql, n4);
        n4 = KVDIM * HIDDEN / 4;
        cvt_split<<<n4 / 256, 256>>>((const float4*)Wk, (uint2*)Wkh, (uint2*)Wkl, n4);
        cvt_split<<<n4 / 256, 256>>>((const float4*)Wv, (uint2*)Wvh, (uint2*)Wvl, n4);
        n4 = HIDDEN * HIDDEN / 4;
        cvt_split<<<n4 / 256, 256>>>((const float4*)Wo, (uint2*)Woh, (uint2*)Wol, n4);
    }

    gemm_tc<<<dim3(HIDDEN / 128, MTOT / 128), 256, SMEM_GEMM>>>(
        xh, xl, Wqh, Wql, Qp, HIDDEN, HIDDEN, nullptr);
    gemm_tc_kv<<<dim3(KVDIM / 128, MTOT / 128, 2), 256, SMEM_GEMM>>>(
        xh, xl, Wkh, Wkl, Wvh, Wvl, Kp, Vp, KVDIM, HIDDEN);
    flash_attn_kernel<<<dim3(SEQ / 64, NHEADS, BATCH), 256, smem_flash>>>();
    {
        int n4 = MTOT * HIDDEN / 4;
        cvt_split<<<n4 / 256, 256>>>((const float4*)Ap, (uint2*)ah, (uint2*)al, n4);
    }
    gemm_tc<<<dim3(HIDDEN / 128, MTOT / 128), 256, SMEM_GEMM>>>(
        ah, al, Woh, Wol, out, HIDDEN, HIDDEN, bo);
}

// round 6
// speedup vs baseline: 3.0414x; 1.8852x over previous
#include <cuda_runtime.h>
#include <cuda_bf16.h>
#include <cstdint>

#define HIDDEN 2048
#define NHEADS 32
#define NKV 8
#define HEAD 64
#define BATCH 2
#define SEQ 2048
#define MTOT (BATCH * SEQ)      // 4096
#define KVDIM (NKV * HEAD)      // 512

// ---------------- scratch (__device__ globals; no allocation allowed) -------
__device__ __nv_bfloat16 g_xh[MTOT * HIDDEN],  g_xl[MTOT * HIDDEN];
__device__ __nv_bfloat16 g_Wqh[HIDDEN * HIDDEN], g_Wql[HIDDEN * HIDDEN];
__device__ __nv_bfloat16 g_Wkh[KVDIM * HIDDEN],  g_Wkl[KVDIM * HIDDEN];
__device__ __nv_bfloat16 g_Wvh[KVDIM * HIDDEN],  g_Wvl[KVDIM * HIDDEN];
__device__ __nv_bfloat16 g_Woh[HIDDEN * HIDDEN], g_Wol[HIDDEN * HIDDEN];
__device__ __nv_bfloat16 g_Qh[MTOT * HIDDEN],  g_Ql[MTOT * HIDDEN];
__device__ __nv_bfloat16 g_Kh[MTOT * KVDIM],   g_Kl[MTOT * KVDIM];
__device__ __nv_bfloat16 g_Vh[MTOT * KVDIM],   g_Vl[MTOT * KVDIM];
__device__ __nv_bfloat16 g_ah[MTOT * HIDDEN],  g_al[MTOT * HIDDEN];

// ---------------- helpers ----------------------------------------------------
__device__ __forceinline__ uint32_t smem_u32(const void* p) {
    uint32_t a;
    asm("{ .reg .u64 t; cvta.to.shared.u64 t, %1; cvt.u32.u64 %0, t; }"
        : "=r"(a) : "l"(p));
    return a;
}
__device__ __forceinline__ float ex2f(float x) {
    float y;
    asm("ex2.approx.ftz.f32 %0, %1;" : "=f"(y) : "f"(x));
    return y;
}
__device__ __forceinline__ uint32_t cvt2bf(float hi, float lo) {
    uint32_t r;
    asm("cvt.rn.bf16x2.f32 %0, %1, %2;" : "=r"(r) : "f"(hi), "f"(lo));
    return r;
}
// split two fp32 (lo-lane c0, hi-lane c1) -> packed bf16x2 hi part + lo part
__device__ __forceinline__ void split2(float c0, float c1,
                                       uint32_t& hp, uint32_t& lp) {
    hp = cvt2bf(c1, c0);
    float h0 = __uint_as_float(hp << 16);
    float h1 = __uint_as_float(hp & 0xffff0000u);
    lp = cvt2bf(c1 - h1, c0 - h0);
}

#define CP16(dst, src) \
    asm volatile("cp.async.cg.shared.global [%0], [%1], 16;" \
                 :: "r"(dst), "l"(src) : "memory")
#define CP_COMMIT() asm volatile("cp.async.commit_group;" ::: "memory")
#define CP_WAIT(N)  asm volatile("cp.async.wait_group %0;" :: "n"(N) : "memory")

__device__ __forceinline__ void ldsm_x4(uint32_t* r, uint32_t addr) {
    asm volatile("ldmatrix.sync.aligned.m8n8.x4.shared.b16 {%0,%1,%2,%3}, [%4];"
                 : "=r"(r[0]), "=r"(r[1]), "=r"(r[2]), "=r"(r[3]) : "r"(addr));
}
__device__ __forceinline__ void ldsm_x4_t(uint32_t* r, uint32_t addr) {
    asm volatile("ldmatrix.sync.aligned.m8n8.x4.trans.shared.b16 {%0,%1,%2,%3}, [%4];"
                 : "=r"(r[0]), "=r"(r[1]), "=r"(r[2]), "=r"(r[3]) : "r"(addr));
}
__device__ __forceinline__ void mma_bf16(float* c, const uint32_t* a,
                                         const uint32_t* b) {
    asm volatile(
        "mma.sync.aligned.m16n8k16.row.col.f32.bf16.bf16.f32 "
        "{%0,%1,%2,%3}, {%4,%5,%6,%7}, {%8,%9}, {%0,%1,%2,%3};"
        : "+f"(c[0]), "+f"(c[1]), "+f"(c[2]), "+f"(c[3])
        : "r"(a[0]), "r"(a[1]), "r"(a[2]), "r"(a[3]), "r"(b[0]), "r"(b[1]));
}

// ---------------------------------------------------------------------------
// fp32 -> (hi, lo) bf16 split
// ---------------------------------------------------------------------------
__global__ void cvt_split(const float4* __restrict__ in,
                          uint2* __restrict__ hi, uint2* __restrict__ lo, int n4) {
    int i = blockIdx.x * blockDim.x + threadIdx.x;
    if (i >= n4) return;
    float4 v = in[i];
    uint2 uh, ul;
    split2(v.x, v.y, uh.x, ul.x);
    split2(v.z, v.w, uh.y, ul.y);
    hi[i] = uh;
    lo[i] = ul;
}

// ---------------------------------------------------------------------------
// mma.sync split-bf16 GEMM (pass-ordered). MODE 0: fp32 out + bias.
// MODE 1: split bf16 hi/lo out.
// ---------------------------------------------------------------------------
#define TSTRIDE 80
#define TILE_B (128 * TSTRIDE)
#define BUF_B  (4 * TILE_B)
#define SMEM_GEMM (2 * BUF_B)            // 81920

template <int MODE>
__device__ __forceinline__ void gemm_tc_body(
    const __nv_bfloat16* __restrict__ Ah, const __nv_bfloat16* __restrict__ Al,
    const __nv_bfloat16* __restrict__ Bh, const __nv_bfloat16* __restrict__ Bl,
    float* __restrict__ C, __nv_bfloat16* __restrict__ Ch,
    __nv_bfloat16* __restrict__ Cl, int N, int K, const float* __restrict__ bias)
{
    extern __shared__ __align__(128) char smem[];
    const int tid = threadIdx.x;
    const int lane = tid & 31;
    const int warp = tid >> 5;
    const int wm = warp >> 2;
    const int wn = warp & 3;
    const int m0 = blockIdx.y * 128;
    const int n0 = blockIdx.x * 128;
    const uint32_t sbase = smem_u32(smem);

    const __nv_bfloat16* gsrc[4] = {Ah, Al, Bh, Bl};
    const int row0[4] = {m0, m0, n0, n0};

    auto load_chunk = [&](int c, int buf) {
        const int k0 = c << 5;
        const uint32_t db = sbase + buf * BUF_B;
#pragma unroll
        for (int i = 0; i < 8; i++) {
            int idx = tid + i * 256;
            int a = idx >> 9;
            int rem = idx & 511;
            int r = rem >> 2;
            int q = rem & 3;
            uint32_t dst = db + a * TILE_B + r * TSTRIDE + q * 16;
            const __nv_bfloat16* src = gsrc[a] + (size_t)(row0[a] + r) * K + k0 + q * 8;
            CP16(dst, src);
        }
        CP_COMMIT();
    };

    float acc[4][4][4];
#pragma unroll
    for (int mt = 0; mt < 4; mt++)
#pragma unroll
        for (int nt = 0; nt < 4; nt++)
#pragma unroll
            for (int j = 0; j < 4; j++) acc[mt][nt][j] = 0.f;

    const int NC = K >> 5;
    load_chunk(0, 0);

    const int a_row = lane & 15;
    const int a_cg  = (lane >> 4) * 16;
    const int b_row = (lane & 7) + ((lane >> 4) << 3);
    const int b_cg  = ((lane >> 3) & 1) * 16;

    for (int c = 0; c < NC; ++c) {
        const int buf = c & 1;
        if (c + 1 < NC) {
            load_chunk(c + 1, buf ^ 1);
            CP_WAIT(1);
        } else {
            CP_WAIT(0);
        }
        __syncthreads();

        const uint32_t db = sbase + buf * BUF_B;
        const uint32_t sAh = db;
        const uint32_t sAl = db + TILE_B;
        const uint32_t sBh = db + 2 * TILE_B;
        const uint32_t sBl = db + 3 * TILE_B;

#pragma unroll
        for (int ks = 0; ks < 2; ks++) {
            const int kb = ks * 32;
            uint32_t aH[4][4], aL[4][4], bH[2][4], bL[2][4];
#pragma unroll
            for (int mt = 0; mt < 4; mt++) {
                uint32_t off = (uint32_t)(wm * 64 + mt * 16 + a_row) * TSTRIDE + a_cg + kb;
                ldsm_x4(aH[mt], sAh + off);
            }
#pragma unroll
            for (int np = 0; np < 2; np++) {
                uint32_t off = (uint32_t)(wn * 32 + np * 16 + b_row) * TSTRIDE + b_cg + kb;
                ldsm_x4(bH[np], sBh + off);
                ldsm_x4(bL[np], sBl + off);
            }
#pragma unroll
            for (int mt = 0; mt < 4; mt++)
#pragma unroll
                for (int np = 0; np < 2; np++) {
                    mma_bf16(acc[mt][2 * np + 0], aH[mt], &bH[np][0]);
                    mma_bf16(acc[mt][2 * np + 1], aH[mt], &bH[np][2]);
                }
#pragma unroll
            for (int mt = 0; mt < 4; mt++)
#pragma unroll
                for (int np = 0; np < 2; np++) {
                    mma_bf16(acc[mt][2 * np + 0], aH[mt], &bL[np][0]);
                    mma_bf16(acc[mt][2 * np + 1], aH[mt], &bL[np][2]);
                }
#pragma unroll
            for (int mt = 0; mt < 4; mt++) {
                uint32_t off = (uint32_t)(wm * 64 + mt * 16 + a_row) * TSTRIDE + a_cg + kb;
                ldsm_x4(aL[mt], sAl + off);
            }
#pragma unroll
            for (int mt = 0; mt < 4; mt++)
#pragma unroll
                for (int np = 0; np < 2; np++) {
                    mma_bf16(acc[mt][2 * np + 0], aL[mt], &bH[np][0]);
                    mma_bf16(acc[mt][2 * np + 1], aL[mt], &bH[np][2]);
                }
        }
        __syncthreads();
    }

    const int frow = lane >> 2;
    const int fcol = (lane & 3) * 2;
#pragma unroll
    for (int mt = 0; mt < 4; mt++) {
#pragma unroll
        for (int nt = 0; nt < 4; nt++) {
            int row = m0 + wm * 64 + mt * 16 + frow;
            int col = n0 + wn * 32 + nt * 8 + fcol;
            if (MODE == 0) {
                float b0 = 0.f, b1 = 0.f;
                if (bias) { b0 = bias[col]; b1 = bias[col + 1]; }
                float2 v0 = make_float2(acc[mt][nt][0] + b0, acc[mt][nt][1] + b1);
                float2 v1 = make_float2(acc[mt][nt][2] + b0, acc[mt][nt][3] + b1);
                *(float2*)(C + (size_t)row * N + col) = v0;
                *(float2*)(C + (size_t)(row + 8) * N + col) = v1;
            } else {
                uint32_t hp, lp;
                split2(acc[mt][nt][0], acc[mt][nt][1], hp, lp);
                *(uint32_t*)(Ch + (size_t)row * N + col) = hp;
                *(uint32_t*)(Cl + (size_t)row * N + col) = lp;
                split2(acc[mt][nt][2], acc[mt][nt][3], hp, lp);
                *(uint32_t*)(Ch + (size_t)(row + 8) * N + col) = hp;
                *(uint32_t*)(Cl + (size_t)(row + 8) * N + col) = lp;
            }
        }
    }
}

__global__ __launch_bounds__(256)
void gemm_tc_f32(const __nv_bfloat16* __restrict__ Ah, const __nv_bfloat16* __restrict__ Al,
                 const __nv_bfloat16* __restrict__ Bh, const __nv_bfloat16* __restrict__ Bl,
                 float* __restrict__ C, int N, int K, const float* __restrict__ bias)
{
    gemm_tc_body<0>(Ah, Al, Bh, Bl, C, nullptr, nullptr, N, K, bias);
}

__global__ __launch_bounds__(256)
void gemm_tc_split(const __nv_bfloat16* __restrict__ Ah, const __nv_bfloat16* __restrict__ Al,
                   const __nv_bfloat16* __restrict__ Bh, const __nv_bfloat16* __restrict__ Bl,
                   __nv_bfloat16* __restrict__ Ch, __nv_bfloat16* __restrict__ Cl,
                   int N, int K)
{
    gemm_tc_body<1>(Ah, Al, Bh, Bl, nullptr, Ch, Cl, N, K, nullptr);
}

__global__ __launch_bounds__(256)
void gemm_tc_kv_split(const __nv_bfloat16* __restrict__ xh, const __nv_bfloat16* __restrict__ xl,
                      const __nv_bfloat16* __restrict__ Wkh, const __nv_bfloat16* __restrict__ Wkl,
                      const __nv_bfloat16* __restrict__ Wvh, const __nv_bfloat16* __restrict__ Wvl,
                      __nv_bfloat16* __restrict__ Kh, __nv_bfloat16* __restrict__ Kl,
                      __nv_bfloat16* __restrict__ Vh, __nv_bfloat16* __restrict__ Vl,
                      int N, int K)
{
    if (blockIdx.z == 0)
        gemm_tc_body<1>(xh, xl, Wkh, Wkl, nullptr, Kh, Kl, N, K, nullptr);
    else
        gemm_tc_body<1>(xh, xl, Wvh, Wvl, nullptr, Vh, Vl, N, K, nullptr);
}

// ---------------------------------------------------------------------------
// Flash attention on mma.sync, split-bf16 (3 passes for both QK^T and PV).
// Br=128, Bc=64, D=64. 8 warps; warp w owns S rows [16w, 16w+16).
// smem: Qh/Ql [128 x 64 bf16] + double-buffered Kh/Kl/Vh/Vl [64 x 64 bf16].
// Row stride 144B -> conflict-free ldmatrix without swizzle.
// ---------------------------------------------------------------------------
#define FTS 144
#define FQ_B (128 * FTS)                  // 18432 per Q part
#define FKV_B (64 * FTS)                  // 9216 per kv part
#define FBUF_B (4 * FKV_B)                // 36864 per kv buffer
#define SMEM_FLASH (2 * FQ_B + 2 * FBUF_B)  // 110592

__global__ __launch_bounds__(256)
void flash_mma_kernel()
{
    extern __shared__ __align__(128) char smem[];
    const int tid = threadIdx.x;
    const int lane = tid & 31;
    const int wid = tid >> 5;
    const int q0 = blockIdx.x * 128;
    const int h  = blockIdx.y;
    const int b  = blockIdx.z;
    const int kvh = h >> 2;
    const uint32_t sbase = smem_u32(smem);
    const uint32_t sQh = sbase, sQl = sbase + FQ_B;
    const uint32_t sBUF = sbase + 2 * FQ_B;

    const float SC = 0.125f * 1.4426950408889634f;

    // ---- load Q (hi/lo), 128 rows x 64 bf16 each
    {
        const __nv_bfloat16* srcs[2] = {g_Qh, g_Ql};
#pragma unroll
        for (int i = 0; i < 8; i++) {
            int idx = tid + i * 256;          // 0..2047
            int arr = idx >> 10;
            int rem = idx & 1023;
            int r = rem >> 3;
            int q = rem & 7;
            uint32_t dst = sbase + arr * FQ_B + r * FTS + q * 16;
            const __nv_bfloat16* src =
                srcs[arr] + (size_t)(b * SEQ + q0 + r) * HIDDEN + h * HEAD + q * 8;
            CP16(dst, src);
        }
    }

    auto load_kv = [&](int c, int buf) {
        const int kv0 = c << 6;
        const uint32_t db = sBUF + buf * FBUF_B;
        const __nv_bfloat16* srcs[4] = {g_Kh, g_Kl, g_Vh, g_Vl};
#pragma unroll
        for (int i = 0; i < 8; i++) {
            int idx = tid + i * 256;          // 0..2047
            int arr = idx >> 9;               // 0..3
            int rem = idx & 511;
            int r = rem >> 3;                 // 0..63
            int q = rem & 7;
            uint32_t dst = db + arr * FKV_B + r * FTS + q * 16;
            const __nv_bfloat16* src =
                srcs[arr] + (size_t)(b * SEQ + kv0 + r) * KVDIM + kvh * HEAD + q * 8;
            CP16(dst, src);
        }
        CP_COMMIT();
    };

    load_kv(0, 0);   // group 0 includes Q chunks issued above

    float m0 = -1e30f, m1 = -1e30f, l0 = 0.f, l1 = 0.f;
    float o[8][4];
#pragma unroll
    for (int ot = 0; ot < 8; ot++)
#pragma unroll
        for (int j = 0; j < 4; j++) o[ot][j] = 0.f;

    const int a_row = lane & 15;
    const int a_cg  = (lane >> 4) * 16;
    const int b_row = (lane & 7) + ((lane >> 4) << 3);
    const int b_cg  = ((lane >> 3) & 1) * 16;
    const uint32_t qoff = (uint32_t)(wid * 16 + a_row) * FTS + a_cg;
    // V trans-ldsm lane addressing
    const int v_row = (lane & 7) + ((lane >> 3) & 1) * 8;
    const int v_cg  = (lane >> 4) * 16;

    const int NITER = SEQ / 64;   // 32
    for (int c = 0; c < NITER; ++c) {
        if (c + 1 < NITER) {
            load_kv(c + 1, (c + 1) & 1);
            CP_WAIT(1);
        } else {
            CP_WAIT(0);
        }
        __syncthreads();

        const uint32_t db = sBUF + (c & 1) * FBUF_B;
        const uint32_t sKh = db, sKl = db + FKV_B;
        const uint32_t sVh = db + 2 * FKV_B, sVl = db + 3 * FKV_B;

        // ---- S = Q K^T (3 passes)
        float s[8][4];
#pragma unroll
        for (int nt = 0; nt < 8; nt++)
#pragma unroll
            for (int j = 0; j < 4; j++) s[nt][j] = 0.f;

#pragma unroll
        for (int ks = 0; ks < 4; ks++) {
            const int kb = ks * 32;
            uint32_t aQh[4], aQl[4], bKh[4][4], bKl[4][4];
            ldsm_x4(aQh, sQh + qoff + kb);
            ldsm_x4(aQl, sQl + qoff + kb);
#pragma unroll
            for (int np = 0; np < 4; np++) {
                uint32_t off = (uint32_t)(np * 16 + b_row) * FTS + b_cg + kb;
                ldsm_x4(bKh[np], sKh + off);
                ldsm_x4(bKl[np], sKl + off);
            }
#pragma unroll
            for (int np = 0; np < 4; np++) {
                mma_bf16(s[2 * np + 0], aQh, &bKh[np][0]);
                mma_bf16(s[2 * np + 1], aQh, &bKh[np][2]);
            }
#pragma unroll
            for (int np = 0; np < 4; np++) {
                mma_bf16(s[2 * np + 0], aQh, &bKl[np][0]);
                mma_bf16(s[2 * np + 1], aQh, &bKl[np][2]);
            }
#pragma unroll
            for (int np = 0; np < 4; np++) {
                mma_bf16(s[2 * np + 0], aQl, &bKh[np][0]);
                mma_bf16(s[2 * np + 1], aQl, &bKh[np][2]);
            }
        }

        // ---- online softmax (base-2, scale folded)
        float mx0 = -1e30f, mx1 = -1e30f;
#pragma unroll
        for (int nt = 0; nt < 8; nt++) {
#pragma unroll
            for (int j = 0; j < 4; j++) s[nt][j] *= SC;
            mx0 = fmaxf(mx0, fmaxf(s[nt][0], s[nt][1]));
            mx1 = fmaxf(mx1, fmaxf(s[nt][2], s[nt][3]));
        }
        mx0 = fmaxf(mx0, __shfl_xor_sync(0xffffffffu, mx0, 1));
        mx0 = fmaxf(mx0, __shfl_xor_sync(0xffffffffu, mx0, 2));
        mx1 = fmaxf(mx1, __shfl_xor_sync(0xffffffffu, mx1, 1));
        mx1 = fmaxf(mx1, __shfl_xor_sync(0xffffffffu, mx1, 2));
        float mn0 = fmaxf(m0, mx0), mn1 = fmaxf(m1, mx1);
        float al0 = ex2f(m0 - mn0), al1 = ex2f(m1 - mn1);
        m0 = mn0; m1 = mn1;

        float rs0 = 0.f, rs1 = 0.f;
        uint32_t aPh[4][4], aPl[4][4];
#pragma unroll
        for (int nt = 0; nt < 8; nt++) {
            float p0 = ex2f(s[nt][0] - m0);
            float p1 = ex2f(s[nt][1] - m0);
            float p2 = ex2f(s[nt][2] - m1);
            float p3 = ex2f(s[nt][3] - m1);
            rs0 += p0 + p1;
            rs1 += p2 + p3;
            const int kt = nt >> 1;
            const int hh = (nt & 1) * 2;
            uint32_t hp, lp;
            split2(p0, p1, hp, lp);
            aPh[kt][hh] = hp; aPl[kt][hh] = lp;
            split2(p2, p3, hp, lp);
            aPh[kt][hh + 1] = hp; aPl[kt][hh + 1] = lp;
        }
        l0 = l0 * al0 + rs0;
        l1 = l1 * al1 + rs1;
#pragma unroll
        for (int ot = 0; ot < 8; ot++) {
            o[ot][0] *= al0; o[ot][1] *= al0;
            o[ot][2] *= al1; o[ot][3] *= al1;
        }

        // ---- O += P V (3 passes), V via ldmatrix.trans
#pragma unroll
        for (int kt = 0; kt < 4; kt++) {
            uint32_t bVh[4][4], bVl[4][4];
            const uint32_t vro = (uint32_t)(kt * 16 + v_row) * FTS + v_cg;
#pragma unroll
            for (int g = 0; g < 4; g++) {
                ldsm_x4_t(bVh[g], sVh + vro + g * 32);
                ldsm_x4_t(bVl[g], sVl + vro + g * 32);
            }
#pragma unroll
            for (int g = 0; g < 4; g++) {
                mma_bf16(o[2 * g + 0], aPh[kt], &bVh[g][0]);
                mma_bf16(o[2 * g + 1], aPh[kt], &bVh[g][2]);
            }
#pragma unroll
            for (int g = 0; g < 4; g++) {
                mma_bf16(o[2 * g + 0], aPh[kt], &bVl[g][0]);
                mma_bf16(o[2 * g + 1], aPh[kt], &bVl[g][2]);
            }
#pragma unroll
            for (int g = 0; g < 4; g++) {
                mma_bf16(o[2 * g + 0], aPl[kt], &bVh[g][0]);
                mma_bf16(o[2 * g + 1], aPl[kt], &bVh[g][2]);
            }
        }
        __syncthreads();   // all warps done with this kv buffer
    }

    // ---- epilogue: normalize, split to bf16 hi/lo, store
    l0 += __shfl_xor_sync(0xffffffffu, l0, 1);
    l0 += __shfl_xor_sync(0xffffffffu, l0, 2);
    l1 += __shfl_xor_sync(0xffffffffu, l1, 1);
    l1 += __shfl_xor_sync(0xffffffffu, l1, 2);
    const float inv0 = 1.f / l0, inv1 = 1.f / l1;

    const int r0 = q0 + wid * 16 + (lane >> 2);
    const int r1 = r0 + 8;
    const int colb = h * HEAD + (lane & 3) * 2;
#pragma unroll
    for (int ot = 0; ot < 8; ot++) {
        const int col = colb + ot * 8;
        uint32_t hp, lp;
        split2(o[ot][0] * inv0, o[ot][1] * inv0, hp, lp);
        *(uint32_t*)(g_ah + (size_t)(b * SEQ + r0) * HIDDEN + col) = hp;
        *(uint32_t*)(g_al + (size_t)(b * SEQ + r0) * HIDDEN + col) = lp;
        split2(o[ot][2] * inv1, o[ot][3] * inv1, hp, lp);
        *(uint32_t*)(g_ah + (size_t)(b * SEQ + r1) * HIDDEN + col) = hp;
        *(uint32_t*)(g_al + (size_t)(b * SEQ + r1) * HIDDEN + col) = lp;
    }
}

// ---------------------------------------------------------------------------

extern "C" void kernel_launch(void* const* d_in, const int* in_sizes, int n_in,
                              void* d_out, int out_size)
{
    const float* x  = (const float*)d_in[0];
    const float* Wq = (const float*)d_in[1];
    const float* Wk = (const float*)d_in[2];
    const float* Wv = (const float*)d_in[3];
    const float* Wo = (const float*)d_in[4];
    const float* bo = (const float*)d_in[5];
    float* out = (float*)d_out;

    __nv_bfloat16 *xh, *xl, *Wqh, *Wql, *Wkh, *Wkl, *Wvh, *Wvl, *Woh, *Wol;
    __nv_bfloat16 *Qh, *Ql, *Kh, *Kl, *Vh, *Vl, *ah, *al;
    cudaGetSymbolAddress((void**)&xh, g_xh);   cudaGetSymbolAddress((void**)&xl, g_xl);
    cudaGetSymbolAddress((void**)&Wqh, g_Wqh); cudaGetSymbolAddress((void**)&Wql, g_Wql);
    cudaGetSymbolAddress((void**)&Wkh, g_Wkh); cudaGetSymbolAddress((void**)&Wkl, g_Wkl);
    cudaGetSymbolAddress((void**)&Wvh, g_Wvh); cudaGetSymbolAddress((void**)&Wvl, g_Wvl);
    cudaGetSymbolAddress((void**)&Woh, g_Woh); cudaGetSymbolAddress((void**)&Wol, g_Wol);
    cudaGetSymbolAddress((void**)&Qh, g_Qh);   cudaGetSymbolAddress((void**)&Ql, g_Ql);
    cudaGetSymbolAddress((void**)&Kh, g_Kh);   cudaGetSymbolAddress((void**)&Kl, g_Kl);
    cudaGetSymbolAddress((void**)&Vh, g_Vh);   cudaGetSymbolAddress((void**)&Vl, g_Vl);
    cudaGetSymbolAddress((void**)&ah, g_ah);   cudaGetSymbolAddress((void**)&al, g_al);

    cudaFuncSetAttribute(gemm_tc_f32, cudaFuncAttributeMaxDynamicSharedMemorySize, SMEM_GEMM);
    cudaFuncSetAttribute(gemm_tc_split, cudaFuncAttributeMaxDynamicSharedMemorySize, SMEM_GEMM);
    cudaFuncSetAttribute(gemm_tc_kv_split, cudaFuncAttributeMaxDynamicSharedMemorySize, SMEM_GEMM);
    cudaFuncSetAttribute(flash_mma_kernel, cudaFuncAttributeMaxDynamicSharedMemorySize, SMEM_FLASH);

    {
        int n4;
        n4 = MTOT * HIDDEN / 4;
        cvt_split<<<n4 / 256, 256>>>((const float4*)x, (uint2*)xh, (uint2*)xl, n4);
        n4 = HIDDEN * HIDDEN / 4;
        cvt_split<<<n4 / 256, 256>>>((const float4*)Wq, (uint2*)Wqh, (uint2*)Wql, n4);
        n4 = KVDIM * HIDDEN / 4;
        cvt_split<<<n4 / 256, 256>>>((const float4*)Wk, (uint2*)Wkh, (uint2*)Wkl, n4);
        cvt_split<<<n4 / 256, 256>>>((const float4*)Wv, (uint2*)Wvh, (uint2*)Wvl, n4);
        n4 = HIDDEN * HIDDEN / 4;
        cvt_split<<<n4 / 256, 256>>>((const float4*)Wo, (uint2*)Woh, (uint2*)Wol, n4);
    }

    // Q projection -> split bf16
    gemm_tc_split<<<dim3(HIDDEN / 128, MTOT / 128), 256, SMEM_GEMM>>>(
        xh, xl, Wqh, Wql, Qh, Ql, HIDDEN, HIDDEN);
    // K,V projections -> split bf16
    gemm_tc_kv_split<<<dim3(KVDIM / 128, MTOT / 128, 2), 256, SMEM_GEMM>>>(
        xh, xl, Wkh, Wkl, Wvh, Wvl, Kh, Kl, Vh, Vl, KVDIM, HIDDEN);
    // attention (tensor-core flash) -> split bf16
    flash_mma_kernel<<<dim3(SEQ / 128, NHEADS, BATCH), 256, SMEM_FLASH>>>();
    // output projection + bias -> fp32
    gemm_tc_f32<<<dim3(HIDDEN / 128, MTOT / 128), 256, SMEM_GEMM>>>(
        ah, al, Woh, Wol, out, HIDDEN, HIDDEN, bo);
}